// round 15
// baseline (speedup 1.0000x reference)
#include <cuda_runtime.h>

typedef unsigned long long u64;

#define NBAT 2
#define SQ 400
#define IW 80
#define HD 128
#define FD 256
#define NP 401
#define NPAD 448
#define KPD 128

__device__ float g_xWi[4 * SQ * 512];
__device__ float g_xp [NBAT * NP * FD];
__device__ float g_cum[NBAT * NPAD * FD];
__device__ float g_pxd[NBAT * NP * KPD];
__device__ float g_pxe[NBAT * NP * KPD];
__device__ float g_W1T[FD * KPD];
__device__ float g_sT [NBAT * NP * NP];

__device__ __forceinline__ float preluf(float x, float a) { return x >= 0.f ? x : a * x; }
__device__ __forceinline__ float sigf(float x) { return 1.f / (1.f + __expf(-x)); }
__device__ __forceinline__ float tanhfast(float x) {
    float xc = fminf(fmaxf(x, -15.f), 15.f);
    float t = __expf(-2.f * xc);
    return (1.f - t) / (1.f + t);
}
__device__ __forceinline__ void ffma2(u64& c, u64 a, u64 b) {
    asm("fma.rn.f32x2 %0, %1, %2, %0;" : "+l"(c) : "l"(a), "l"(b));
}
__device__ __forceinline__ u64 dupf(float x) {
    u64 r; asm("mov.b64 %0, {%1, %1};" : "=l"(r) : "f"(x)); return r;
}
__device__ __forceinline__ float2 unpk(u64 u) {
    float2 r; asm("mov.b64 {%0, %1}, %2;" : "=f"(r.x), "=f"(r.y) : "l"(u)); return r;
}
__device__ __forceinline__ float psum(u64 u) {
    float2 r = unpk(u); return r.x + r.y;
}

// ---- launch 1: W1c transpose ----
__global__ void k_w1t(const float* __restrict__ W1) {
    int idx = blockIdx.x * 256 + threadIdx.x;
    int f = idx >> 7, k = idx & 127;
    g_W1T[idx] = (k < 100) ? W1[k * 768 + f] : 0.f;
}

// ---- launch 2: xWi = x @ Wi^T + b ----
__global__ void k_xwi(const float* __restrict__ x, const float* __restrict__ Wif,
                      const float* __restrict__ bf, const float* __restrict__ Wib,
                      const float* __restrict__ bbv) {
    int t = blockIdx.x, ch = blockIdx.y, d = ch >> 1, bb = ch & 1;
    const float* Wi = d ? Wib : Wif;
    const float* bi = d ? bbv : bf;
    __shared__ __align__(16) float sx[IW];
    int g = threadIdx.x;
    if (g < IW) sx[g] = x[(bb * SQ + t) * IW + g];
    __syncthreads();
    float acc = bi[g];
    const float4* wr = (const float4*)(Wi + g * IW);
    const float4* xr = (const float4*)sx;
#pragma unroll
    for (int q = 0; q < IW / 4; q++) {
        float4 w = wr[q], xv = xr[q];
        acc += w.x * xv.x + w.y * xv.y + w.z * xv.z + w.w * xv.w;
    }
    g_xWi[(ch * SQ + t) * 512 + g] = acc;
}

// ---- launch 3: zero g_cum padding rows ----
#define PADROWS (NPAD - NP)
__global__ void k_pad() {
    int idx = blockIdx.x * 256 + threadIdx.x;
    if (idx < NBAT * PADROWS * FD) {
        int b = idx / (PADROWS * FD);
        int r = idx - b * (PADROWS * FD);
        g_cum[b * NPAD * FD + NP * FD + r] = 0.f;
    }
}

// ---- launch 4 (PROFILED): LSTM, unroll-4 j-loop to kill spills ----
#define LSTM_SMEM (65536 + 2048)

__global__ void __launch_bounds__(256, 1)
k_lstm(const float* __restrict__ Whf, const float* __restrict__ Whb) {
    int chain = blockIdx.x;
    int d = chain >> 1, b = chain & 1;
    const float* Wh = d ? Whb : Whf;
    extern __shared__ __align__(16) float lsm[];
    float4* sWo = (float4*)lsm;
    float*  hb  = lsm + 16384;
    int t = threadIdx.x;
    int u = t >> 1, half = t & 1;

    for (int idx = t; idx < 16 * 256; idx += 256) {
        int q = idx >> 8, pr = idx & 255;
        int uu = pr >> 1, hh = pr & 1;
        sWo[idx] = *(const float4*)(Wh + (384 + uu) * 128 + hh * 64 + q * 4);
    }
    u64 wi[32], wf[32], wg[32];
    {
        const u64* si = (const u64*)(Wh + u * 128 + half * 64);
        const u64* sf = (const u64*)(Wh + (128 + u) * 128 + half * 64);
        const u64* sg = (const u64*)(Wh + (256 + u) * 128 + half * 64);
#pragma unroll
        for (int j = 0; j < 32; j++) { wi[j] = si[j]; wf[j] = sf[j]; wg[j] = sg[j]; }
    }
    if (t < 136) { hb[t] = 0.f; hb[136 + t] = 0.f; }
    float cst = 0.f;
    __syncthreads();

    const float* xw = g_xWi + (chain * SQ) * 512;
    float* xpo = g_xp + (b * NP) * FD + d * HD;
    int tt0 = d ? (SQ - 1) : 0;
    float xwi_ = 0.f, xwf_ = 0.f, xwg_ = 0.f, xwo_ = 0.f;
    if (half == 0) {
        xwi_ = xw[tt0 * 512 + u];       xwf_ = xw[tt0 * 512 + 128 + u];
        xwg_ = xw[tt0 * 512 + 256 + u]; xwo_ = xw[tt0 * 512 + 384 + u];
    }

    for (int s = 0; s < SQ; s++) {
        int tt = d ? (SQ - 1 - s) : s;
        const ulonglong2* hv = (const ulonglong2*)(hb + (s & 1) * 136 + half * 68);
        u64 ai0 = 0, ai1 = 0, af0 = 0, af1 = 0, ag0 = 0, ag1 = 0, ao0 = 0, ao1 = 0;
#pragma unroll 4
        for (int j = 0; j < 16; j++) {
            ulonglong2 h2 = hv[j];
            float4 wo4 = sWo[j * 256 + t];
            ulonglong2 wo2 = *(ulonglong2*)&wo4;
            ffma2(ai0, h2.x, wi[2 * j]); ffma2(ai1, h2.y, wi[2 * j + 1]);
            ffma2(af0, h2.x, wf[2 * j]); ffma2(af1, h2.y, wf[2 * j + 1]);
            ffma2(ag0, h2.x, wg[2 * j]); ffma2(ag1, h2.y, wg[2 * j + 1]);
            ffma2(ao0, h2.x, wo2.x);     ffma2(ao1, h2.y, wo2.y);
        }
        float gi = psum(ai0) + psum(ai1);
        float gf = psum(af0) + psum(af1);
        float gg = psum(ag0) + psum(ag1);
        float go = psum(ao0) + psum(ao1);
        gi += __shfl_xor_sync(0xffffffffu, gi, 1);
        gf += __shfl_xor_sync(0xffffffffu, gf, 1);
        gg += __shfl_xor_sync(0xffffffffu, gg, 1);
        go += __shfl_xor_sync(0xffffffffu, go, 1);
        if (half == 0) {
            float iv = sigf(gi + xwi_);
            float fv = sigf(gf + xwf_);
            float gv = tanhfast(gg + xwg_);
            float ov = sigf(go + xwo_);
            cst = fv * cst + iv * gv;
            float h = ov * tanhfast(cst);
            xpo[(tt + 1) * FD + u] = h;
            int nb = (s + 1) & 1;
            hb[nb * 136 + ((u < 64) ? u : (68 + u - 64))] = h;
            if (s + 1 < SQ) {
                int tn = d ? (SQ - 2 - s) : (s + 1);
                xwi_ = xw[tn * 512 + u];       xwf_ = xw[tn * 512 + 128 + u];
                xwg_ = xw[tn * 512 + 256 + u]; xwo_ = xw[tn * 512 + 384 + u];
            }
        }
        __syncthreads();
    }
}

// ---- launch 5: fused pxde + heads + cumsum ----
__global__ void __launch_bounds__(256)
k_mid(const float* __restrict__ W1, const float* __restrict__ b1,
      const float* __restrict__ a1,
      const float* __restrict__ Wc1, const float* __restrict__ bc1,
      const float* __restrict__ Wc2, const float* __restrict__ bc2,
      const float* __restrict__ Wb1, const float* __restrict__ bb1,
      const float* __restrict__ Wb2, const float* __restrict__ bb2,
      const float* __restrict__ ac1, const float* __restrict__ ac2,
      const float* __restrict__ ab1, const float* __restrict__ ab2,
      float* __restrict__ oc, float* __restrict__ ob) {
    int blk = blockIdx.x;
    int tid = threadIdx.x;
    if (blk < 802) {
        int b = blk / NP, n = blk - b * NP;
        __shared__ __align__(16) float sx[FD];
        float A = a1[0];
        sx[tid] = preluf(g_xp[(b * NP + n) * FD + tid], A);
        __syncthreads();
        int k = tid & 127, which = tid >> 7;
        float* dst = (which ? g_pxe : g_pxd) + (b * NP + n) * KPD + k;
        if (k >= 100) { *dst = 0.f; return; }
        const float4* wr = (const float4*)(W1 + k * 768 + (which ? 512 : 256));
        const float4* xr = (const float4*)sx;
        float acc = which ? 0.f : b1[k];
#pragma unroll 16
        for (int q = 0; q < 64; q++) {
            float4 w = wr[q], xv = xr[q];
            acc += w.x * xv.x + w.y * xv.y + w.z * xv.z + w.w * xv.w;
        }
        *dst = acc;
    } else if (blk < 1602) {
        int idx = blk - 802;
        int b = idx / SQ, t = idx - b * SQ;
        __shared__ __align__(16) float prc[FD], prb[FD], hc[100], hb2[100];
        float x = g_xp[(b * NP + t + 1) * FD + tid];
        prc[tid] = preluf(x, ac1[0]);
        prb[tid] = preluf(x, ab1[0]);
        __syncthreads();
        if (tid < 100) {
            float acc = bc1[tid];
            const float4* wr = (const float4*)(Wc1 + tid * FD);
            const float4* xr = (const float4*)prc;
#pragma unroll 8
            for (int q = 0; q < 64; q++) {
                float4 wv = wr[q], xv = xr[q];
                acc += wv.x*xv.x + wv.y*xv.y + wv.z*xv.z + wv.w*xv.w;
            }
            hc[tid] = preluf(acc, ac2[0]);
        } else if (tid >= 128 && tid < 228) {
            int k = tid - 128;
            float acc = bb1[k];
            const float4* wr = (const float4*)(Wb1 + k * FD);
            const float4* xr = (const float4*)prb;
#pragma unroll 8
            for (int q = 0; q < 64; q++) {
                float4 wv = wr[q], xv = xr[q];
                acc += wv.x*xv.x + wv.y*xv.y + wv.z*xv.z + wv.w*xv.w;
            }
            hb2[k] = preluf(acc, ab2[0]);
        }
        __syncthreads();
        if (tid < 50) {
            float acc = bc2[tid];
            for (int q = 0; q < 100; q++) acc += Wc2[tid * 100 + q] * hc[q];
            oc[(b * SQ + t) * 50 + tid] = acc;
        } else if (tid >= 64 && tid < 66) {
            int r = tid - 64;
            float acc = bb2[r];
            for (int q = 0; q < 100; q++) acc += Wb2[r * 100 + q] * hb2[q];
            ob[(b * SQ + t) * 2 + r] = acc;
        }
    } else {
        int b = blk - 1602;
        int f = tid;
        float* xp = g_xp + b * NP * FD + f;
        float* cm = g_cum + b * NPAD * FD + f;
        xp[0] = 0.f; cm[0] = 0.f;
        float a = 0.f;
        for (int n = 1; n <= SQ; n += 8) {
            float v0 = xp[(n + 0) * FD], v1 = xp[(n + 1) * FD];
            float v2 = xp[(n + 2) * FD], v3 = xp[(n + 3) * FD];
            float v4 = xp[(n + 4) * FD], v5 = xp[(n + 5) * FD];
            float v6 = xp[(n + 6) * FD], v7 = xp[(n + 7) * FD];
            a += v0; cm[(n + 0) * FD] = a;
            a += v1; cm[(n + 1) * FD] = a;
            a += v2; cm[(n + 2) * FD] = a;
            a += v3; cm[(n + 3) * FD] = a;
            a += v4; cm[(n + 4) * FD] = a;
            a += v5; cm[(n + 5) * FD] = a;
            a += v6; cm[(n + 6) * FD] = a;
            a += v7; cm[(n + 7) * FD] = a;
        }
    }
}

// ---- launch 6: span-scoring (R14 proven: 512 threads) ----
#define JW 14
#define VSTR 226
#define OFF_V   32768
#define OFF_CI  (OFF_V + 64 * VSTR)
#define OFF_PXD (OFF_CI + 256)
#define OFF_W2  (OFF_PXD + 128)
#define SMEM_FLOATS (OFF_W2 + 128)

__global__ void __launch_bounds__(512, 1)
k_scores(const float* __restrict__ W2, const float* __restrict__ b2,
         const float* __restrict__ a1p, const float* __restrict__ a2p,
         float* __restrict__ outp) {
    extern __shared__ __align__(16) float sm[];
    float* sW  = sm;
    float* sV  = sm + OFF_V;
    float* sCI = sm + OFF_CI;
    float* sPD = sm + OFF_PXD;
    float* sW2 = sm + OFF_W2;
    int i = blockIdx.x, b = blockIdx.y, tid = threadIdx.x;
    int w = tid >> 5, l = tid & 31;
    float A1 = a1p[0], A2 = a2p[0], B2 = b2[0];
    for (int idx = tid; idx < 32768; idx += 512) sW[idx] = g_W1T[idx];
    if (tid < 256) sCI[tid] = g_cum[(b * NPAD + i) * FD + tid];
    if (tid >= 256 && tid < 384) {
        int k = tid - 256;
        sPD[k] = g_pxd[(b * NP + i) * KPD + k];
        sW2[k] = (k < 100) ? W2[k] : 0.f;
    }
    for (int pass = 0; pass < 2; pass++) {
        int jbase = pass * 224;
        int j0w = jbase + w * JW;
        u64 acc[7][4];
#pragma unroll
        for (int jp = 0; jp < 7; jp++) { acc[jp][0]=0; acc[jp][1]=0; acc[jp][2]=0; acc[jp][3]=0; }
        for (int fc = 0; fc < 4; fc++) {
            __syncthreads();
            for (int idx = tid; idx < 224 * 64; idx += 512) {
                int jl = idx >> 6, fl = idx & 63;
                int f = fc * 64 + fl;
                sV[fl * VSTR + jl] = preluf(g_cum[(b * NPAD + jbase + jl) * FD + f] - sCI[f], A1);
            }
            __syncthreads();
            const float* sWf = sW + (fc * 64) * 128;
            for (int f = 0; f < 64; f++) {
                const u64* vr = (const u64*)(sV + f * VSTR + w * JW);
                float4 wv = ((const float4*)(sWf + f * 128))[l];
                u64 d0 = dupf(wv.x), d1 = dupf(wv.y), d2 = dupf(wv.z), d3 = dupf(wv.w);
#pragma unroll
                for (int jp = 0; jp < 7; jp++) {
                    u64 v = vr[jp];
                    ffma2(acc[jp][0], v, d0); ffma2(acc[jp][1], v, d1);
                    ffma2(acc[jp][2], v, d2); ffma2(acc[jp][3], v, d3);
                }
            }
        }
#pragma unroll
        for (int jp = 0; jp < 7; jp++) {
            float2 u0 = unpk(acc[jp][0]), u1 = unpk(acc[jp][1]);
            float2 u2 = unpk(acc[jp][2]), u3 = unpk(acc[jp][3]);
#pragma unroll
            for (int half = 0; half < 2; half++) {
                int j = j0w + 2 * jp + half;
                float s = 0.f;
                if (j < NP) {
                    float4 pe = *(const float4*)(g_pxe + (b * NP + j) * KPD + 4 * l);
                    float a0 = half ? u0.y : u0.x, a1v = half ? u1.y : u1.x;
                    float a2v = half ? u2.y : u2.x, a3 = half ? u3.y : u3.x;
                    float h0 = a0 + sPD[4*l]   + pe.x;
                    float h1 = a1v + sPD[4*l+1] + pe.y;
                    float h2 = a2v + sPD[4*l+2] + pe.z;
                    float h3 = a3 + sPD[4*l+3] + pe.w;
                    s = preluf(h0,A2)*sW2[4*l] + preluf(h1,A2)*sW2[4*l+1]
                      + preluf(h2,A2)*sW2[4*l+2] + preluf(h3,A2)*sW2[4*l+3];
                }
#pragma unroll
                for (int off = 16; off; off >>= 1) s += __shfl_xor_sync(0xffffffffu, s, off);
                if (j < NP && l == 0) {
                    float r = s + B2;
                    outp[(b * NP + i) * NP + j] = r;
                    g_sT[(b * NP + j) * NP + i] = r;
                }
            }
        }
    }
}

// ---- launch 7: banded Viterbi DP ----
__global__ void k_dp(const int* __restrict__ lengths, float* __restrict__ outp) {
    int b = threadIdx.x >> 5, l = threadIdx.x & 31;
    __shared__ float best[NBAT][NP];
    for (int n = l; n < NP; n += 32) best[b][n] = 0.f;
    float* prevrow = outp + 363204 + b * NP;
    float* preds   = outp + 363202;
    if (l == 0) prevrow[0] = 0.f;
    __syncwarp();
    const float* sT = g_sT + b * NP * NP;
    float p0 = sT[1 * NP + l];
    float p1 = sT[1 * NP + (l + 32 > NP - 1 ? NP - 1 : l + 32)];
    for (int i = 1; i < NP; i++) {
        int k0 = i - 50; if (k0 < 0) k0 = 0;
        int cnt = i - k0;
        float c0 = (l < cnt)      ? best[b][k0 + l]      + p0 : -1e30f;
        float c1 = (l + 32 < cnt) ? best[b][k0 + l + 32] + p1 : -1e30f;
        if (i + 1 < NP) {
            int kn = i + 1 - 50; if (kn < 0) kn = 0;
            int i2 = kn + l + 32; if (i2 > NP - 1) i2 = NP - 1;
            p0 = sT[(i + 1) * NP + kn + l];
            p1 = sT[(i + 1) * NP + i2];
        }
        float v = c0; int kk = k0 + l;
        if (c1 > v) { v = c1; kk = k0 + l + 32; }
#pragma unroll
        for (int off = 16; off; off >>= 1) {
            float v2 = __shfl_xor_sync(0xffffffffu, v, off);
            int k2 = __shfl_xor_sync(0xffffffffu, kk, off);
            if (v2 > v || (v2 == v && k2 < kk)) { v = v2; kk = k2; }
        }
        if (l == 0) { best[b][i] = v; prevrow[i] = (float)kk; }
        __syncwarp();
    }
    if (l == 0) preds[b] = best[b][lengths[b]];
}

extern "C" void kernel_launch(void* const* d_in, const int* in_sizes, int n_in,
                              void* d_out, int out_size) {
    const float* x    = (const float*)d_in[0];
    const int*   len  = (const int*)  d_in[1];
    const float* Wif  = (const float*)d_in[2];
    const float* Whf  = (const float*)d_in[3];
    const float* bf   = (const float*)d_in[4];
    const float* Wib  = (const float*)d_in[5];
    const float* Whb  = (const float*)d_in[6];
    const float* bbv  = (const float*)d_in[7];
    const float* a1   = (const float*)d_in[8];
    const float* W1   = (const float*)d_in[9];
    const float* b1   = (const float*)d_in[10];
    const float* a2   = (const float*)d_in[11];
    const float* W2   = (const float*)d_in[12];
    const float* b2   = (const float*)d_in[13];
    const float* ac1  = (const float*)d_in[14];
    const float* Wc1  = (const float*)d_in[15];
    const float* bc1  = (const float*)d_in[16];
    const float* ac2  = (const float*)d_in[17];
    const float* Wc2  = (const float*)d_in[18];
    const float* bc2  = (const float*)d_in[19];
    const float* ab1  = (const float*)d_in[20];
    const float* Wb1  = (const float*)d_in[21];
    const float* bb1  = (const float*)d_in[22];
    const float* ab2  = (const float*)d_in[23];
    const float* Wb2  = (const float*)d_in[24];
    const float* bb2  = (const float*)d_in[25];
    float* out = (float*)d_out;

    static int smem_set = 0;
    if (!smem_set) {
        cudaFuncSetAttribute(k_scores, cudaFuncAttributeMaxDynamicSharedMemorySize,
                             SMEM_FLOATS * 4);
        cudaFuncSetAttribute(k_lstm, cudaFuncAttributeMaxDynamicSharedMemorySize,
                             LSTM_SMEM);
        smem_set = 1;
    }

    k_w1t<<<128, 256>>>(W1);
    k_xwi<<<dim3(SQ, 4), 512>>>(x, Wif, bf, Wib, bbv);
    k_pad<<<94, 256>>>();
    k_lstm<<<4, 256, LSTM_SMEM>>>(Whf, Whb);
    k_mid<<<1604, 256>>>(W1, b1, a1, Wc1, bc1, Wc2, bc2, Wb1, bb1, Wb2, bb2,
                         ac1, ac2, ab1, ab2, out + 321602, out + 361602);
    k_scores<<<dim3(NP, NBAT), 512, SMEM_FLOATS * 4>>>(W2, b2, a1, a2, out);
    k_dp<<<1, 64>>>(len, out);
}

// round 16
// speedup vs baseline: 1.3442x; 1.3442x over previous
#include <cuda_runtime.h>

typedef unsigned long long u64;

#define NBAT 2
#define SQ 400
#define IW 80
#define HD 128
#define FD 256
#define NP 401
#define NPAD 448
#define KPD 128

__device__ float g_xWi[4 * SQ * 512];
__device__ float g_xp [NBAT * NP * FD];
__device__ float g_cum[NBAT * NPAD * FD];
__device__ float g_pxd[NBAT * NP * KPD];
__device__ float g_pxe[NBAT * NP * KPD];
__device__ float g_W1T[FD * KPD];
__device__ float g_sT [NBAT * NP * NP];

__device__ __forceinline__ float preluf(float x, float a) { return x >= 0.f ? x : a * x; }
__device__ __forceinline__ float sigf(float x) { return 1.f / (1.f + __expf(-x)); }
__device__ __forceinline__ float tanhfast(float x) {
    float xc = fminf(fmaxf(x, -15.f), 15.f);
    float t = __expf(-2.f * xc);
    return (1.f - t) / (1.f + t);
}
__device__ __forceinline__ void ffma2(u64& c, u64 a, u64 b) {
    asm("fma.rn.f32x2 %0, %1, %2, %0;" : "+l"(c) : "l"(a), "l"(b));
}
__device__ __forceinline__ u64 dupf(float x) {
    u64 r; asm("mov.b64 %0, {%1, %1};" : "=l"(r) : "f"(x)); return r;
}
__device__ __forceinline__ float2 unpk(u64 u) {
    float2 r; asm("mov.b64 {%0, %1}, %2;" : "=f"(r.x), "=f"(r.y) : "l"(u)); return r;
}
__device__ __forceinline__ float psum(u64 u) {
    float2 r = unpk(u); return r.x + r.y;
}

// ---- launch 1: W1c transpose ----
__global__ void k_w1t(const float* __restrict__ W1) {
    int idx = blockIdx.x * 256 + threadIdx.x;
    int f = idx >> 7, k = idx & 127;
    g_W1T[idx] = (k < 100) ? W1[k * 768 + f] : 0.f;
}

// ---- launch 2: xWi = x @ Wi^T + b ----
__global__ void k_xwi(const float* __restrict__ x, const float* __restrict__ Wif,
                      const float* __restrict__ bf, const float* __restrict__ Wib,
                      const float* __restrict__ bbv) {
    int t = blockIdx.x, ch = blockIdx.y, d = ch >> 1, bb = ch & 1;
    const float* Wi = d ? Wib : Wif;
    const float* bi = d ? bbv : bf;
    __shared__ __align__(16) float sx[IW];
    int g = threadIdx.x;
    if (g < IW) sx[g] = x[(bb * SQ + t) * IW + g];
    __syncthreads();
    float acc = bi[g];
    const float4* wr = (const float4*)(Wi + g * IW);
    const float4* xr = (const float4*)sx;
#pragma unroll
    for (int q = 0; q < IW / 4; q++) {
        float4 w = wr[q], xv = xr[q];
        acc += w.x * xv.x + w.y * xv.y + w.z * xv.z + w.w * xv.w;
    }
    g_xWi[(ch * SQ + t) * 512 + g] = acc;
}

// ---- launch 3: zero g_cum padding rows ----
#define PADROWS (NPAD - NP)
__global__ void k_pad() {
    int idx = blockIdx.x * 256 + threadIdx.x;
    if (idx < NBAT * PADROWS * FD) {
        int b = idx / (PADROWS * FD);
        int r = idx - b * (PADROWS * FD);
        g_cum[b * NPAD * FD + NP * FD + r] = 0.f;
    }
}

// ---- launch 4 (PROFILED): LSTM — R13 proven full-unroll version ----
#define LSTM_SMEM (65536 + 2048)

__global__ void __launch_bounds__(256, 1)
k_lstm(const float* __restrict__ Whf, const float* __restrict__ Whb) {
    int chain = blockIdx.x;
    int d = chain >> 1, b = chain & 1;
    const float* Wh = d ? Whb : Whf;
    extern __shared__ __align__(16) float lsm[];
    float4* sWo = (float4*)lsm;
    float*  hb  = lsm + 16384;
    int t = threadIdx.x;
    int u = t >> 1, half = t & 1;

    for (int idx = t; idx < 16 * 256; idx += 256) {
        int q = idx >> 8, pr = idx & 255;
        int uu = pr >> 1, hh = pr & 1;
        sWo[idx] = *(const float4*)(Wh + (384 + uu) * 128 + hh * 64 + q * 4);
    }
    u64 wi[32], wf[32], wg[32];
    {
        const u64* si = (const u64*)(Wh + u * 128 + half * 64);
        const u64* sf = (const u64*)(Wh + (128 + u) * 128 + half * 64);
        const u64* sg = (const u64*)(Wh + (256 + u) * 128 + half * 64);
#pragma unroll
        for (int j = 0; j < 32; j++) { wi[j] = si[j]; wf[j] = sf[j]; wg[j] = sg[j]; }
    }
    if (t < 136) { hb[t] = 0.f; hb[136 + t] = 0.f; }
    float cst = 0.f;
    __syncthreads();

    const float* xw = g_xWi + (chain * SQ) * 512;
    float* xpo = g_xp + (b * NP) * FD + d * HD;
    int tt0 = d ? (SQ - 1) : 0;
    float xwi_ = 0.f, xwf_ = 0.f, xwg_ = 0.f, xwo_ = 0.f;
    if (half == 0) {
        xwi_ = xw[tt0 * 512 + u];       xwf_ = xw[tt0 * 512 + 128 + u];
        xwg_ = xw[tt0 * 512 + 256 + u]; xwo_ = xw[tt0 * 512 + 384 + u];
    }

    for (int s = 0; s < SQ; s++) {
        int tt = d ? (SQ - 1 - s) : s;
        const ulonglong2* hv = (const ulonglong2*)(hb + (s & 1) * 136 + half * 68);
        u64 ai0 = 0, ai1 = 0, af0 = 0, af1 = 0, ag0 = 0, ag1 = 0, ao0 = 0, ao1 = 0;
#pragma unroll
        for (int j = 0; j < 16; j++) {
            ulonglong2 h2 = hv[j];
            float4 wo4 = sWo[j * 256 + t];
            ulonglong2 wo2 = *(ulonglong2*)&wo4;
            ffma2(ai0, h2.x, wi[2 * j]); ffma2(ai1, h2.y, wi[2 * j + 1]);
            ffma2(af0, h2.x, wf[2 * j]); ffma2(af1, h2.y, wf[2 * j + 1]);
            ffma2(ag0, h2.x, wg[2 * j]); ffma2(ag1, h2.y, wg[2 * j + 1]);
            ffma2(ao0, h2.x, wo2.x);     ffma2(ao1, h2.y, wo2.y);
        }
        float gi = psum(ai0) + psum(ai1);
        float gf = psum(af0) + psum(af1);
        float gg = psum(ag0) + psum(ag1);
        float go = psum(ao0) + psum(ao1);
        gi += __shfl_xor_sync(0xffffffffu, gi, 1);
        gf += __shfl_xor_sync(0xffffffffu, gf, 1);
        gg += __shfl_xor_sync(0xffffffffu, gg, 1);
        go += __shfl_xor_sync(0xffffffffu, go, 1);
        if (half == 0) {
            float iv = sigf(gi + xwi_);
            float fv = sigf(gf + xwf_);
            float gv = tanhfast(gg + xwg_);
            float ov = sigf(go + xwo_);
            cst = fv * cst + iv * gv;
            float h = ov * tanhfast(cst);
            xpo[(tt + 1) * FD + u] = h;
            int nb = (s + 1) & 1;
            hb[nb * 136 + ((u < 64) ? u : (68 + u - 64))] = h;
            if (s + 1 < SQ) {
                int tn = d ? (SQ - 2 - s) : (s + 1);
                xwi_ = xw[tn * 512 + u];       xwf_ = xw[tn * 512 + 128 + u];
                xwg_ = xw[tn * 512 + 256 + u]; xwo_ = xw[tn * 512 + 384 + u];
            }
        }
        __syncthreads();
    }
}

// ---- launch 5: fused pxde + heads + cumsum ----
__global__ void __launch_bounds__(256)
k_mid(const float* __restrict__ W1, const float* __restrict__ b1,
      const float* __restrict__ a1,
      const float* __restrict__ Wc1, const float* __restrict__ bc1,
      const float* __restrict__ Wc2, const float* __restrict__ bc2,
      const float* __restrict__ Wb1, const float* __restrict__ bb1,
      const float* __restrict__ Wb2, const float* __restrict__ bb2,
      const float* __restrict__ ac1, const float* __restrict__ ac2,
      const float* __restrict__ ab1, const float* __restrict__ ab2,
      float* __restrict__ oc, float* __restrict__ ob) {
    int blk = blockIdx.x;
    int tid = threadIdx.x;
    if (blk < 802) {
        int b = blk / NP, n = blk - b * NP;
        __shared__ __align__(16) float sx[FD];
        float A = a1[0];
        sx[tid] = preluf(g_xp[(b * NP + n) * FD + tid], A);
        __syncthreads();
        int k = tid & 127, which = tid >> 7;
        float* dst = (which ? g_pxe : g_pxd) + (b * NP + n) * KPD + k;
        if (k >= 100) { *dst = 0.f; return; }
        const float4* wr = (const float4*)(W1 + k * 768 + (which ? 512 : 256));
        const float4* xr = (const float4*)sx;
        float acc = which ? 0.f : b1[k];
#pragma unroll 16
        for (int q = 0; q < 64; q++) {
            float4 w = wr[q], xv = xr[q];
            acc += w.x * xv.x + w.y * xv.y + w.z * xv.z + w.w * xv.w;
        }
        *dst = acc;
    } else if (blk < 1602) {
        int idx = blk - 802;
        int b = idx / SQ, t = idx - b * SQ;
        __shared__ __align__(16) float prc[FD], prb[FD], hc[100], hb2[100];
        float x = g_xp[(b * NP + t + 1) * FD + tid];
        prc[tid] = preluf(x, ac1[0]);
        prb[tid] = preluf(x, ab1[0]);
        __syncthreads();
        if (tid < 100) {
            float acc = bc1[tid];
            const float4* wr = (const float4*)(Wc1 + tid * FD);
            const float4* xr = (const float4*)prc;
#pragma unroll 8
            for (int q = 0; q < 64; q++) {
                float4 wv = wr[q], xv = xr[q];
                acc += wv.x*xv.x + wv.y*xv.y + wv.z*xv.z + wv.w*xv.w;
            }
            hc[tid] = preluf(acc, ac2[0]);
        } else if (tid >= 128 && tid < 228) {
            int k = tid - 128;
            float acc = bb1[k];
            const float4* wr = (const float4*)(Wb1 + k * FD);
            const float4* xr = (const float4*)prb;
#pragma unroll 8
            for (int q = 0; q < 64; q++) {
                float4 wv = wr[q], xv = xr[q];
                acc += wv.x*xv.x + wv.y*xv.y + wv.z*xv.z + wv.w*xv.w;
            }
            hb2[k] = preluf(acc, ab2[0]);
        }
        __syncthreads();
        if (tid < 50) {
            float acc = bc2[tid];
            for (int q = 0; q < 100; q++) acc += Wc2[tid * 100 + q] * hc[q];
            oc[(b * SQ + t) * 50 + tid] = acc;
        } else if (tid >= 64 && tid < 66) {
            int r = tid - 64;
            float acc = bb2[r];
            for (int q = 0; q < 100; q++) acc += Wb2[r * 100 + q] * hb2[q];
            ob[(b * SQ + t) * 2 + r] = acc;
        }
    } else {
        int b = blk - 1602;
        int f = tid;
        float* xp = g_xp + b * NP * FD + f;
        float* cm = g_cum + b * NPAD * FD + f;
        xp[0] = 0.f; cm[0] = 0.f;
        float a = 0.f;
        for (int n = 1; n <= SQ; n += 8) {
            float v0 = xp[(n + 0) * FD], v1 = xp[(n + 1) * FD];
            float v2 = xp[(n + 2) * FD], v3 = xp[(n + 3) * FD];
            float v4 = xp[(n + 4) * FD], v5 = xp[(n + 5) * FD];
            float v6 = xp[(n + 6) * FD], v7 = xp[(n + 7) * FD];
            a += v0; cm[(n + 0) * FD] = a;
            a += v1; cm[(n + 1) * FD] = a;
            a += v2; cm[(n + 2) * FD] = a;
            a += v3; cm[(n + 3) * FD] = a;
            a += v4; cm[(n + 4) * FD] = a;
            a += v5; cm[(n + 5) * FD] = a;
            a += v6; cm[(n + 6) * FD] = a;
            a += v7; cm[(n + 7) * FD] = a;
        }
    }
}

// ---- launch 6: span-scoring, templated pass (pass0: JW=14, pass1: JW=12) ----
#define VSTR 226
#define OFF_V   32768
#define OFF_CI  (OFF_V + 64 * VSTR)
#define OFF_PXD (OFF_CI + 256)
#define OFF_W2  (OFF_PXD + 128)
#define SMEM_FLOATS (OFF_W2 + 128)

template<int JPH>
__device__ __forceinline__ void score_pass(
    int jbase, int i, int b, int tid, int w, int l,
    float A1, float A2, float B2,
    float* sW, float* sV, float* sCI, float* sPD, float* sW2,
    float* __restrict__ outp) {
    const int JW = 2 * JPH;
    const int JT = 16 * JW;
    int j0w = jbase + w * JW;
    u64 acc[JPH][4];
#pragma unroll
    for (int jp = 0; jp < JPH; jp++) { acc[jp][0]=0; acc[jp][1]=0; acc[jp][2]=0; acc[jp][3]=0; }
    for (int fc = 0; fc < 4; fc++) {
        __syncthreads();
        for (int idx = tid; idx < JT * 64; idx += 512) {
            int jl = idx / 64, fl = idx & 63;
            int f = fc * 64 + fl;
            sV[fl * VSTR + jl] = preluf(g_cum[(b * NPAD + jbase + jl) * FD + f] - sCI[f], A1);
        }
        __syncthreads();
        const float* sWf = sW + (fc * 64) * 128;
        for (int f = 0; f < 64; f++) {
            const u64* vr = (const u64*)(sV + f * VSTR + w * JW);
            float4 wv = ((const float4*)(sWf + f * 128))[l];
            u64 d0 = dupf(wv.x), d1 = dupf(wv.y), d2 = dupf(wv.z), d3 = dupf(wv.w);
#pragma unroll
            for (int jp = 0; jp < JPH; jp++) {
                u64 v = vr[jp];
                ffma2(acc[jp][0], v, d0); ffma2(acc[jp][1], v, d1);
                ffma2(acc[jp][2], v, d2); ffma2(acc[jp][3], v, d3);
            }
        }
    }
#pragma unroll
    for (int jp = 0; jp < JPH; jp++) {
        float2 u0 = unpk(acc[jp][0]), u1 = unpk(acc[jp][1]);
        float2 u2 = unpk(acc[jp][2]), u3 = unpk(acc[jp][3]);
#pragma unroll
        for (int half = 0; half < 2; half++) {
            int j = j0w + 2 * jp + half;
            float s = 0.f;
            if (j < NP) {
                float4 pe = *(const float4*)(g_pxe + (b * NP + j) * KPD + 4 * l);
                float a0 = half ? u0.y : u0.x, a1v = half ? u1.y : u1.x;
                float a2v = half ? u2.y : u2.x, a3 = half ? u3.y : u3.x;
                float h0 = a0 + sPD[4*l]   + pe.x;
                float h1 = a1v + sPD[4*l+1] + pe.y;
                float h2 = a2v + sPD[4*l+2] + pe.z;
                float h3 = a3 + sPD[4*l+3] + pe.w;
                s = preluf(h0,A2)*sW2[4*l] + preluf(h1,A2)*sW2[4*l+1]
                  + preluf(h2,A2)*sW2[4*l+2] + preluf(h3,A2)*sW2[4*l+3];
            }
#pragma unroll
            for (int off = 16; off; off >>= 1) s += __shfl_xor_sync(0xffffffffu, s, off);
            if (j < NP && l == 0) {
                float r = s + B2;
                outp[(b * NP + i) * NP + j] = r;
                g_sT[(b * NP + j) * NP + i] = r;
            }
        }
    }
}

__global__ void __launch_bounds__(512, 1)
k_scores(const float* __restrict__ W2, const float* __restrict__ b2,
         const float* __restrict__ a1p, const float* __restrict__ a2p,
         float* __restrict__ outp) {
    extern __shared__ __align__(16) float sm[];
    float* sW  = sm;
    float* sV  = sm + OFF_V;
    float* sCI = sm + OFF_CI;
    float* sPD = sm + OFF_PXD;
    float* sW2 = sm + OFF_W2;
    int i = blockIdx.x, b = blockIdx.y, tid = threadIdx.x;
    int w = tid >> 5, l = tid & 31;
    float A1 = a1p[0], A2 = a2p[0], B2 = b2[0];
    for (int idx = tid; idx < 32768; idx += 512) sW[idx] = g_W1T[idx];
    if (tid < 256) sCI[tid] = g_cum[(b * NPAD + i) * FD + tid];
    if (tid >= 256 && tid < 384) {
        int k = tid - 256;
        sPD[k] = g_pxd[(b * NP + i) * KPD + k];
        sW2[k] = (k < 100) ? W2[k] : 0.f;
    }
    score_pass<7>(0,   i, b, tid, w, l, A1, A2, B2, sW, sV, sCI, sPD, sW2, outp);
    score_pass<6>(224, i, b, tid, w, l, A1, A2, B2, sW, sV, sCI, sPD, sW2, outp);
}

// ---- launch 7: banded Viterbi DP ----
__global__ void k_dp(const int* __restrict__ lengths, float* __restrict__ outp) {
    int b = threadIdx.x >> 5, l = threadIdx.x & 31;
    __shared__ float best[NBAT][NP];
    for (int n = l; n < NP; n += 32) best[b][n] = 0.f;
    float* prevrow = outp + 363204 + b * NP;
    float* preds   = outp + 363202;
    if (l == 0) prevrow[0] = 0.f;
    __syncwarp();
    const float* sT = g_sT + b * NP * NP;
    float p0 = sT[1 * NP + l];
    float p1 = sT[1 * NP + (l + 32 > NP - 1 ? NP - 1 : l + 32)];
    for (int i = 1; i < NP; i++) {
        int k0 = i - 50; if (k0 < 0) k0 = 0;
        int cnt = i - k0;
        float c0 = (l < cnt)      ? best[b][k0 + l]      + p0 : -1e30f;
        float c1 = (l + 32 < cnt) ? best[b][k0 + l + 32] + p1 : -1e30f;
        if (i + 1 < NP) {
            int kn = i + 1 - 50; if (kn < 0) kn = 0;
            int i2 = kn + l + 32; if (i2 > NP - 1) i2 = NP - 1;
            p0 = sT[(i + 1) * NP + kn + l];
            p1 = sT[(i + 1) * NP + i2];
        }
        float v = c0; int kk = k0 + l;
        if (c1 > v) { v = c1; kk = k0 + l + 32; }
#pragma unroll
        for (int off = 16; off; off >>= 1) {
            float v2 = __shfl_xor_sync(0xffffffffu, v, off);
            int k2 = __shfl_xor_sync(0xffffffffu, kk, off);
            if (v2 > v || (v2 == v && k2 < kk)) { v = v2; kk = k2; }
        }
        if (l == 0) { best[b][i] = v; prevrow[i] = (float)kk; }
        __syncwarp();
    }
    if (l == 0) preds[b] = best[b][lengths[b]];
}

extern "C" void kernel_launch(void* const* d_in, const int* in_sizes, int n_in,
                              void* d_out, int out_size) {
    const float* x    = (const float*)d_in[0];
    const int*   len  = (const int*)  d_in[1];
    const float* Wif  = (const float*)d_in[2];
    const float* Whf  = (const float*)d_in[3];
    const float* bf   = (const float*)d_in[4];
    const float* Wib  = (const float*)d_in[5];
    const float* Whb  = (const float*)d_in[6];
    const float* bbv  = (const float*)d_in[7];
    const float* a1   = (const float*)d_in[8];
    const float* W1   = (const float*)d_in[9];
    const float* b1   = (const float*)d_in[10];
    const float* a2   = (const float*)d_in[11];
    const float* W2   = (const float*)d_in[12];
    const float* b2   = (const float*)d_in[13];
    const float* ac1  = (const float*)d_in[14];
    const float* Wc1  = (const float*)d_in[15];
    const float* bc1  = (const float*)d_in[16];
    const float* ac2  = (const float*)d_in[17];
    const float* Wc2  = (const float*)d_in[18];
    const float* bc2  = (const float*)d_in[19];
    const float* ab1  = (const float*)d_in[20];
    const float* Wb1  = (const float*)d_in[21];
    const float* bb1  = (const float*)d_in[22];
    const float* ab2  = (const float*)d_in[23];
    const float* Wb2  = (const float*)d_in[24];
    const float* bb2  = (const float*)d_in[25];
    float* out = (float*)d_out;

    static int smem_set = 0;
    if (!smem_set) {
        cudaFuncSetAttribute(k_scores, cudaFuncAttributeMaxDynamicSharedMemorySize,
                             SMEM_FLOATS * 4);
        cudaFuncSetAttribute(k_lstm, cudaFuncAttributeMaxDynamicSharedMemorySize,
                             LSTM_SMEM);
        smem_set = 1;
    }

    k_w1t<<<128, 256>>>(W1);
    k_xwi<<<dim3(SQ, 4), 512>>>(x, Wif, bf, Wib, bbv);
    k_pad<<<94, 256>>>();
    k_lstm<<<4, 256, LSTM_SMEM>>>(Whf, Whb);
    k_mid<<<1604, 256>>>(W1, b1, a1, Wc1, bc1, Wc2, bc2, Wb1, bb1, Wb2, bb2,
                         ac1, ac2, ab1, ab2, out + 321602, out + 361602);
    k_scores<<<dim3(NP, NBAT), 512, SMEM_FLOATS * 4>>>(W2, b2, a1, a2, out);
    k_dp<<<1, 64>>>(len, out);
}